// round 8
// baseline (speedup 1.0000x reference)
#include <cuda_runtime.h>
#include <cuda_fp16.h>
#include <cstdint>

// 1-NN: out[m] = Y_train[argmin_n (t2[n] - 2*<x_m, t_n>)]
// cross via 3-term fp16 split: A=[hi|lo|hi], B=[hi|hi|lo], K=768,
// computed with warp-level mma.sync.m16n8k16 (base sm_103 target: no tcgen05).

#define B_ROWS   2048
#define N_TRAIN  50000
#define N_PAD    50048        // 391 * 128
#define FEAT     256
#define KAUG     768
#define OUTD     24
#define MT       128
#define NT_TILES 391
#define NSTRIPS  9
#define TPS      44           // ceil(391/9)
#define NCH      12           // K chunks of 64 halves

// smem layout (dynamic)
#define SM_T2    0                      // 128 floats
#define SM_EX    512                    // 128 x (float,int) = 1024 B
#define SM_A     2048                   // 12 chunks x 16384 (SW128, resident)
#define SM_B     (2048 + 12*16384)     // 198656 ; 2 x 16384 double buffer
#define SMEM_BYTES (SM_B + 2*16384)    // 231424 <= 232448

__device__ __align__(16) __half g_Ah[(size_t)B_ROWS * KAUG];
__device__ __align__(16) __half g_Bh[(size_t)N_PAD * KAUG];
__device__ float g_t2[N_PAD];
__device__ float g_pval[(size_t)B_ROWS * NSTRIPS];
__device__ int   g_pidx[(size_t)B_ROWS * NSTRIPS];

// ---------------- PTX helpers (all base-arch legal) ----------------
__device__ __forceinline__ uint32_t smem_u32(const void* p) {
    uint32_t a;
    asm("{ .reg .u64 t; cvta.to.shared.u64 t, %1; cvt.u32.u64 %0, t; }"
        : "=r"(a) : "l"(p));
    return a;
}

#define CP_ASYNC16(dst, src) \
    asm volatile("cp.async.cg.shared.global [%0], [%1], 16;" :: "r"(dst), "l"(src) : "memory")
#define CP_COMMIT() asm volatile("cp.async.commit_group;" ::: "memory")
#define CP_WAIT1()  asm volatile("cp.async.wait_group 1;" ::: "memory")

// non-trans ldmatrix: thread t holds (row = t/4, colpair = (t%4)*2) of each 8x8
// tile.  Used for A ([M][K] row-major) AND for B ([N][K]: gives the required
// col-major B fragment (k=(t%4)*2+{0,1}, n=t/4)).  NO .trans anywhere.
#define LDSM_X4(r, addr)                                                        \
    asm volatile("ldmatrix.sync.aligned.m8n8.x4.shared.b16 {%0,%1,%2,%3}, [%4];" \
                 : "=r"((r)[0]), "=r"((r)[1]), "=r"((r)[2]), "=r"((r)[3])        \
                 : "r"(addr))

__device__ __forceinline__ void mma16816(float* d, const uint32_t* a,
                                         const uint32_t* b) {
    asm volatile(
        "mma.sync.aligned.m16n8k16.row.col.f32.f16.f16.f32 "
        "{%0,%1,%2,%3}, {%4,%5,%6,%7}, {%8,%9}, {%0,%1,%2,%3};"
        : "+f"(d[0]), "+f"(d[1]), "+f"(d[2]), "+f"(d[3])
        : "r"(a[0]), "r"(a[1]), "r"(a[2]), "r"(a[3]), "r"(b[0]), "r"(b[1]));
}

// swizzled byte offset within a 128x64-half SW128 chunk
__device__ __forceinline__ uint32_t swz(int r, int sg) {
    return (uint32_t)(r * 128 + ((sg ^ (r & 7)) << 4));
}

// ---------------- prep: fp16 hi/lo split ----------------
__global__ void prep_query(const float* __restrict__ X) {
    int w = threadIdx.x >> 5, l = threadIdx.x & 31;
    int row = blockIdx.x * 8 + w;                    // 256*8 = 2048
    const float4* src = reinterpret_cast<const float4*>(X + (size_t)row * FEAT);
    float4 a = src[l * 2], b = src[l * 2 + 1];
    float xs[8] = {a.x, a.y, a.z, a.w, b.x, b.y, b.z, b.w};
    __align__(16) __half h[8];
    __align__(16) __half lo[8];
#pragma unroll
    for (int j = 0; j < 8; j++) {
        __half hh = __float2half_rn(xs[j]);
        h[j]  = hh;
        lo[j] = __float2half_rn(xs[j] - __half2float(hh));
    }
    uint4 hv = *reinterpret_cast<uint4*>(h);
    uint4 lv = *reinterpret_cast<uint4*>(lo);
    uint4* dst = reinterpret_cast<uint4*>(g_Ah + (size_t)row * KAUG);
    dst[l]      = hv;   // hi
    dst[32 + l] = lv;   // lo
    dst[64 + l] = hv;   // hi
}

__global__ void prep_train(const float* __restrict__ X) {
    int w = threadIdx.x >> 5, l = threadIdx.x & 31;
    int row = blockIdx.x * 8 + w;                    // 6256*8 = 50048
    __align__(16) __half h[8];
    __align__(16) __half lo[8];
    if (row < N_TRAIN) {
        const float4* src = reinterpret_cast<const float4*>(X + (size_t)row * FEAT);
        float4 a = src[l * 2], b = src[l * 2 + 1];
        float xs[8] = {a.x, a.y, a.z, a.w, b.x, b.y, b.z, b.w};
        float ss = 0.f;
#pragma unroll
        for (int j = 0; j < 8; j++) {
            ss += xs[j] * xs[j];
            __half hh = __float2half_rn(xs[j]);
            h[j]  = hh;
            lo[j] = __float2half_rn(xs[j] - __half2float(hh));
        }
#pragma unroll
        for (int off = 16; off; off >>= 1)
            ss += __shfl_xor_sync(0xffffffffu, ss, off);
        if (l == 0) g_t2[row] = ss;
    } else {
#pragma unroll
        for (int j = 0; j < 8; j++) {
            h[j] = __ushort_as_half((unsigned short)0);
            lo[j] = h[j];
        }
        if (l == 0) g_t2[row] = 1.0e30f;
    }
    uint4 hv = *reinterpret_cast<uint4*>(h);
    uint4 lv = *reinterpret_cast<uint4*>(lo);
    uint4* dst = reinterpret_cast<uint4*>(g_Bh + (size_t)row * KAUG);
    dst[l]      = hv;   // hi
    dst[32 + l] = hv;   // hi
    dst[64 + l] = lv;   // lo
}

// ---------------- fused GEMM + argmin ----------------
__global__ void __launch_bounds__(256, 1) knn_main() {
    extern __shared__ char smem[];
    const uint32_t sb = smem_u32(smem);
    const int tid  = threadIdx.x;
    const int wid  = tid >> 5;
    const int lane = tid & 31;
    const int warp_m = wid >> 1;          // 0..3 -> rows 32*warp_m
    const int warp_n = wid & 1;           // 0..1 -> cols 64*warp_n
    const int m0 = blockIdx.x * MT;

    // ---- resident A tile: 12 SW128 chunks of 128x64 halves ----
    {
        const uint4* As = reinterpret_cast<const uint4*>(g_Ah);
#pragma unroll 4
        for (int i = 0; i < 48; i++) {
            int idx = tid + (i << 8);            // 0..12287
            int ch = idx >> 10;
            int r  = (idx >> 3) & 127;
            int sg = idx & 7;
            uint4 v = As[(size_t)(m0 + r) * 96 + ch * 8 + sg];
            *reinterpret_cast<uint4*>(smem + SM_A + ch * 16384 + swz(r, sg)) = v;
        }
    }

    const int t0 = blockIdx.y * TPS;
    int t1 = t0 + TPS; if (t1 > NT_TILES) t1 = NT_TILES;
    const int nchunks = (t1 - t0) * NCH;

    const uint4* Bs = reinterpret_cast<const uint4*>(g_Bh);

    // per-thread B cp.async coordinates (4 segs of 16B)
    int brow[4], bsg[4];
    uint32_t bdoff[4];
#pragma unroll
    for (int i = 0; i < 4; i++) {
        int idx = tid + (i << 8);
        brow[i] = idx >> 3;
        bsg[i]  = idx & 7;
        bdoff[i] = swz(brow[i], bsg[i]);
    }

    // issue chunk gc (guarded), always commit
    auto issue = [&](int gc) {
        if (gc < nchunks) {
            int tt = t0 + gc / NCH;
            int cc = gc % NCH;
            int n0 = tt << 7;
            uint32_t bb = sb + SM_B + (uint32_t)(gc & 1) * 16384u;
#pragma unroll
            for (int i = 0; i < 4; i++) {
                uint32_t dst = bb + bdoff[i];
                const uint4* src = Bs + (size_t)(n0 + brow[i]) * 96 + cc * 8 + bsg[i];
                CP_ASYNC16(dst, src);
            }
        }
        CP_COMMIT();
    };

    issue(0);
    issue(1);

    // running best per thread: [mf][rr]
    float rbv[2][2] = {{3.0e38f, 3.0e38f}, {3.0e38f, 3.0e38f}};
    int   rbi[2][2] = {{0x7fffffff, 0x7fffffff}, {0x7fffffff, 0x7fffffff}};

    float* t2s = reinterpret_cast<float*>(smem + SM_T2);
    float* exv = reinterpret_cast<float*>(smem + SM_EX);
    int*   exi = reinterpret_cast<int*>(smem + SM_EX + 512);

    // ldmatrix lane coordinates
    const int laA = lane & 15;            // A row within 16
    const int lsA = lane >> 4;            // A k-seg select
    const int laB = (lane & 7) + ((lane >> 4) & 1) * 8;   // B row within 16
    const int lsB = (lane >> 3) & 1;      // B k-seg select
    const uint32_t sbB = sb + SM_B;
    const uint32_t sbA = sb + SM_A;

    int gc = 0;
    for (int t = t0; t < t1; t++) {
        const int n0 = t << 7;
        if (tid < 128) t2s[tid] = g_t2[n0 + tid];

        float acc[2][8][4];
#pragma unroll
        for (int mf = 0; mf < 2; mf++)
#pragma unroll
            for (int nf = 0; nf < 8; nf++)
#pragma unroll
                for (int q = 0; q < 4; q++) acc[mf][nf][q] = 0.f;

        for (int c = 0; c < NCH; c++, gc++) {
            CP_WAIT1();
            __syncthreads();               // buf (gc&1) ready; t2 visible

            const uint32_t ab = sbA + (uint32_t)c * 16384u;
            const uint32_t bb = sbB + (uint32_t)(gc & 1) * 16384u;
#pragma unroll
            for (int ks = 0; ks < 4; ks++) {
                uint32_t a0[4], a1[4], bfr[4][4];
                {
                    int r = warp_m * 32 + laA;
                    int sg = ks * 2 + lsA;
                    LDSM_X4(a0, ab + swz(r, sg));
                    r += 16;
                    LDSM_X4(a1, ab + swz(r, sg));
                }
#pragma unroll
                for (int nfp = 0; nfp < 4; nfp++) {
                    int r = warp_n * 64 + nfp * 16 + laB;
                    int sg = ks * 2 + lsB;
                    LDSM_X4(bfr[nfp], bb + swz(r, sg));   // non-trans: [N][K] -> B frag
                }
#pragma unroll
                for (int nf = 0; nf < 8; nf++) {
                    const uint32_t* bp = &bfr[nf >> 1][(nf & 1) * 2];
                    mma16816(acc[0][nf], a0, bp);
                    mma16816(acc[1][nf], a1, bp);
                }
            }
            __syncthreads();               // all warps done reading buf (gc&1)
            issue(gc + 2);                 // refill it
        }

        // ---- epilogue: d = t2 - 2*acc, fused argmin ----
        const int cbase = warp_n * 64 + (lane & 3) * 2;
#pragma unroll
        for (int mf = 0; mf < 2; mf++) {
#pragma unroll
            for (int rr = 0; rr < 2; rr++) {
                float v = 3.0e38f;
                int vi = 0x7fffffff;
#pragma unroll
                for (int nf = 0; nf < 8; nf++) {
                    int col = cbase + nf * 8;
                    float d0 = fmaf(-2.0f, acc[mf][nf][rr * 2 + 0], t2s[col]);
                    float d1 = fmaf(-2.0f, acc[mf][nf][rr * 2 + 1], t2s[col + 1]);
                    if (d0 < v) { v = d0; vi = n0 + col; }
                    if (d1 < v) { v = d1; vi = n0 + col + 1; }
                }
                // quad reduce (lanes differing in bits 0-1 share the row)
#pragma unroll
                for (int off = 1; off <= 2; off <<= 1) {
                    float ov = __shfl_xor_sync(0xffffffffu, v, off);
                    int   oi = __shfl_xor_sync(0xffffffffu, vi, off);
                    if (ov < v || (ov == v && oi < vi)) { v = ov; vi = oi; }
                }
                int row = warp_m * 32 + mf * 16 + (lane >> 2) + rr * 8;
                if (warp_n == 1) {
                    if ((lane & 3) == 0) { exv[row] = v; exi[row] = vi; }
                } else {
                    if (v < rbv[mf][rr] || (v == rbv[mf][rr] && vi < rbi[mf][rr])) {
                        rbv[mf][rr] = v; rbi[mf][rr] = vi;
                    }
                }
            }
        }
        __syncthreads();
        if (warp_n == 0) {
#pragma unroll
            for (int mf = 0; mf < 2; mf++) {
#pragma unroll
                for (int rr = 0; rr < 2; rr++) {
                    int row = warp_m * 32 + mf * 16 + (lane >> 2) + rr * 8;
                    float ov = exv[row];
                    int   oi = exi[row];
                    if (ov < rbv[mf][rr] ||
                        (ov == rbv[mf][rr] && oi < rbi[mf][rr])) {
                        rbv[mf][rr] = ov; rbi[mf][rr] = oi;
                    }
                }
            }
        }
        __syncthreads();   // EX consumed before next tile's epilogue rewrites it
    }

    if (warp_n == 0 && (lane & 3) == 0) {
#pragma unroll
        for (int mf = 0; mf < 2; mf++)
#pragma unroll
            for (int rr = 0; rr < 2; rr++) {
                int row = m0 + warp_m * 32 + mf * 16 + (lane >> 2) + rr * 8;
                g_pval[(size_t)row * NSTRIPS + blockIdx.y] = rbv[mf][rr];
                g_pidx[(size_t)row * NSTRIPS + blockIdx.y] = rbi[mf][rr];
            }
    }
}

// ---------------- reduce strips + gather Y ----------------
__global__ void reduce_gather(const float* __restrict__ Y, float* __restrict__ out) {
    int warp = (int)((blockIdx.x * blockDim.x + threadIdx.x) >> 5);  // 0..2047
    int lane = threadIdx.x & 31;
    float v = 3.0e38f;
    int idx = 0x7fffffff;
    if (lane < NSTRIPS) {
        v   = g_pval[(size_t)warp * NSTRIPS + lane];
        idx = g_pidx[(size_t)warp * NSTRIPS + lane];
    }
#pragma unroll
    for (int off = 16; off; off >>= 1) {
        float ov = __shfl_xor_sync(0xffffffffu, v, off);
        int   oi = __shfl_xor_sync(0xffffffffu, idx, off);
        if (ov < v || (ov == v && oi < idx)) { v = ov; idx = oi; }
    }
    if (lane < OUTD)
        out[(size_t)warp * OUTD + lane] = Y[(size_t)idx * OUTD + lane];
}

// ---------------- launch ----------------
extern "C" void kernel_launch(void* const* d_in, const int* in_sizes, int n_in,
                              void* d_out, int out_size) {
    const float* x  = (const float*)d_in[0];     // [2048, 256]
    const float* Xt = (const float*)d_in[1];     // [50000, 256]
    const float* Yt = (const float*)d_in[2];     // [50000, 24]
    float* out = (float*)d_out;                  // [2048, 24]
    (void)in_sizes; (void)n_in; (void)out_size;

    cudaFuncSetAttribute(knn_main, cudaFuncAttributeMaxDynamicSharedMemorySize,
                         SMEM_BYTES);

    prep_query<<<B_ROWS / 8, 256>>>(x);
    prep_train<<<N_PAD / 8, 256>>>(Xt);
    dim3 grid(B_ROWS / MT, NSTRIPS);
    knn_main<<<grid, 256, SMEM_BYTES>>>();
    reduce_gather<<<B_ROWS / 8, 256>>>(Yt, out);
}

// round 12
// speedup vs baseline: 1.0339x; 1.0339x over previous
#include <cuda_runtime.h>
#include <cuda_fp16.h>
#include <cstdint>

// 1-NN: out[m] = Y_train[argmin_n (t2[n] - 2*<x_m, t_n>)]
// cross via 3-term fp16 split: A=[hi|lo] (hi reused for 3rd term), B=[hi|hi|lo],
// K=768, warp-level mma.sync.m16n8k16 (base sm_103 target: no tcgen05).
// 4-stage cp.async pipeline, ONE __syncthreads per K-chunk.

#define B_ROWS   2048
#define N_TRAIN  50000
#define N_PAD    50048        // 391 * 128
#define FEAT     256
#define KA_A     512          // A stores [hi|lo] only
#define KAUG     768          // B stores [hi|hi|lo]
#define OUTD     24
#define MT       128
#define NT_TILES 391
#define NSTRIPS  9
#define TPS      44           // ceil(391/9)
#define NCH      12           // K chunks of 64 halves (B side)
#define NSTAGES  4

// smem layout (dynamic)
#define SM_T2    0                      // 128 floats
#define SM_EX    512                    // 128 x (float,int) = 1024 B
#define SM_A     2048                   // 8 chunks x 16384 (SW128, resident)
#define SM_B     (2048 + 8*16384)       // 133120 ; 4 x 16384 ring
#define SMEM_BYTES (SM_B + NSTAGES*16384)   // 198656

__device__ __align__(16) __half g_Ah[(size_t)B_ROWS * KA_A];
__device__ __align__(16) __half g_Bh[(size_t)N_PAD * KAUG];
__device__ float g_t2[N_PAD];
__device__ float g_pval[(size_t)B_ROWS * NSTRIPS];
__device__ int   g_pidx[(size_t)B_ROWS * NSTRIPS];

// ---------------- PTX helpers (base-arch legal) ----------------
__device__ __forceinline__ uint32_t smem_u32(const void* p) {
    uint32_t a;
    asm("{ .reg .u64 t; cvta.to.shared.u64 t, %1; cvt.u32.u64 %0, t; }"
        : "=r"(a) : "l"(p));
    return a;
}

#define CP_ASYNC16(dst, src) \
    asm volatile("cp.async.cg.shared.global [%0], [%1], 16;" :: "r"(dst), "l"(src) : "memory")
#define CP_COMMIT() asm volatile("cp.async.commit_group;" ::: "memory")
#define CP_WAIT2()  asm volatile("cp.async.wait_group 2;" ::: "memory")

// non-trans ldmatrix: for A ([M][K]) gives the A fragment; for B ([N][K],
// K contiguous) gives exactly the required col-major B fragment.
#define LDSM_X4(r, addr)                                                        \
    asm volatile("ldmatrix.sync.aligned.m8n8.x4.shared.b16 {%0,%1,%2,%3}, [%4];" \
                 : "=r"((r)[0]), "=r"((r)[1]), "=r"((r)[2]), "=r"((r)[3])        \
                 : "r"(addr))

__device__ __forceinline__ void mma16816(float* d, const uint32_t* a,
                                         const uint32_t* b) {
    asm volatile(
        "mma.sync.aligned.m16n8k16.row.col.f32.f16.f16.f32 "
        "{%0,%1,%2,%3}, {%4,%5,%6,%7}, {%8,%9}, {%0,%1,%2,%3};"
        : "+f"(d[0]), "+f"(d[1]), "+f"(d[2]), "+f"(d[3])
        : "r"(a[0]), "r"(a[1]), "r"(a[2]), "r"(a[3]), "r"(b[0]), "r"(b[1]));
}

// swizzled byte offset within a 128x64-half SW128 chunk
__device__ __forceinline__ uint32_t swz(int r, int sg) {
    return (uint32_t)(r * 128 + ((sg ^ (r & 7)) << 4));
}

// ---------------- prep: fp16 hi/lo split ----------------
__global__ void prep_query(const float* __restrict__ X) {
    int w = threadIdx.x >> 5, l = threadIdx.x & 31;
    int row = blockIdx.x * 8 + w;                    // 256*8 = 2048
    const float4* src = reinterpret_cast<const float4*>(X + (size_t)row * FEAT);
    float4 a = src[l * 2], b = src[l * 2 + 1];
    float xs[8] = {a.x, a.y, a.z, a.w, b.x, b.y, b.z, b.w};
    __align__(16) __half h[8];
    __align__(16) __half lo[8];
#pragma unroll
    for (int j = 0; j < 8; j++) {
        __half hh = __float2half_rn(xs[j]);
        h[j]  = hh;
        lo[j] = __float2half_rn(xs[j] - __half2float(hh));
    }
    uint4 hv = *reinterpret_cast<uint4*>(h);
    uint4 lv = *reinterpret_cast<uint4*>(lo);
    uint4* dst = reinterpret_cast<uint4*>(g_Ah + (size_t)row * KA_A);
    dst[l]      = hv;   // hi  (k 0..255)
    dst[32 + l] = lv;   // lo  (k 256..511)
}

__global__ void prep_train(const float* __restrict__ X) {
    int w = threadIdx.x >> 5, l = threadIdx.x & 31;
    int row = blockIdx.x * 8 + w;                    // 6256*8 = 50048
    __align__(16) __half h[8];
    __align__(16) __half lo[8];
    if (row < N_TRAIN) {
        const float4* src = reinterpret_cast<const float4*>(X + (size_t)row * FEAT);
        float4 a = src[l * 2], b = src[l * 2 + 1];
        float xs[8] = {a.x, a.y, a.z, a.w, b.x, b.y, b.z, b.w};
        float ss = 0.f;
#pragma unroll
        for (int j = 0; j < 8; j++) {
            ss += xs[j] * xs[j];
            __half hh = __float2half_rn(xs[j]);
            h[j]  = hh;
            lo[j] = __float2half_rn(xs[j] - __half2float(hh));
        }
#pragma unroll
        for (int off = 16; off; off >>= 1)
            ss += __shfl_xor_sync(0xffffffffu, ss, off);
        if (l == 0) g_t2[row] = ss;
    } else {
#pragma unroll
        for (int j = 0; j < 8; j++) {
            h[j] = __ushort_as_half((unsigned short)0);
            lo[j] = h[j];
        }
        if (l == 0) g_t2[row] = 1.0e30f;
    }
    uint4 hv = *reinterpret_cast<uint4*>(h);
    uint4 lv = *reinterpret_cast<uint4*>(lo);
    uint4* dst = reinterpret_cast<uint4*>(g_Bh + (size_t)row * KAUG);
    dst[l]      = hv;   // hi
    dst[32 + l] = hv;   // hi
    dst[64 + l] = lv;   // lo
}

// ---------------- fused GEMM + argmin ----------------
__global__ void __launch_bounds__(256, 1) knn_main() {
    extern __shared__ char smem[];
    const uint32_t sb = smem_u32(smem);
    const int tid  = threadIdx.x;
    const int wid  = tid >> 5;
    const int lane = tid & 31;
    const int warp_m = wid >> 1;          // 0..3 -> rows 32*warp_m
    const int warp_n = wid & 1;           // 0..1 -> cols 64*warp_n
    const int m0 = blockIdx.x * MT;

    const int t0 = blockIdx.y * TPS;
    int t1 = t0 + TPS; if (t1 > NT_TILES) t1 = NT_TILES;
    const int nchunks = (t1 - t0) * NCH;

    const uint4* Bs = reinterpret_cast<const uint4*>(g_Bh);

    // per-thread B cp.async coordinates (4 segs of 16B)
    int brow[4], bsg[4];
    uint32_t bdoff[4];
#pragma unroll
    for (int i = 0; i < 4; i++) {
        int idx = tid + (i << 8);
        brow[i] = idx >> 3;
        bsg[i]  = idx & 7;
        bdoff[i] = swz(brow[i], bsg[i]);
    }

    // issue chunk gc (guarded), always commit (keeps group accounting exact)
    auto issue = [&](int gc) {
        if (gc < nchunks) {
            int tt = t0 + gc / NCH;
            int cc = gc % NCH;
            int n0 = tt << 7;
            uint32_t bb = sb + SM_B + (uint32_t)(gc % NSTAGES) * 16384u;
#pragma unroll
            for (int i = 0; i < 4; i++) {
                uint32_t dst = bb + bdoff[i];
                const uint4* src = Bs + (size_t)(n0 + brow[i]) * 96 + cc * 8 + bsg[i];
                CP_ASYNC16(dst, src);
            }
        }
        CP_COMMIT();
    };

    issue(0); issue(1); issue(2);

    // ---- resident A tile: 8 SW128 chunks of 128x64 halves ([hi|lo]) ----
    {
        const uint4* As = reinterpret_cast<const uint4*>(g_Ah);
#pragma unroll 4
        for (int i = 0; i < 32; i++) {
            int idx = tid + (i << 8);            // 0..8191
            int ch = idx >> 10;                  // 0..7
            int r  = (idx >> 3) & 127;
            int sg = idx & 7;
            uint4 v = As[(size_t)(m0 + r) * 64 + ch * 8 + sg];
            *reinterpret_cast<uint4*>(smem + SM_A + ch * 16384 + swz(r, sg)) = v;
        }
    }

    // running best per thread: [mf][rr]
    float rbv[2][2] = {{3.0e38f, 3.0e38f}, {3.0e38f, 3.0e38f}};
    int   rbi[2][2] = {{0x7fffffff, 0x7fffffff}, {0x7fffffff, 0x7fffffff}};

    float* t2s = reinterpret_cast<float*>(smem + SM_T2);
    float* exv = reinterpret_cast<float*>(smem + SM_EX);
    int*   exi = reinterpret_cast<int*>(smem + SM_EX + 512);

    // ldmatrix lane coordinates
    const int laA = lane & 15;            // A row within 16
    const int lsA = lane >> 4;            // A k-seg select
    const int laB = (lane & 7) + ((lane >> 4) & 1) * 8;   // B row within 16
    const int lsB = (lane >> 3) & 1;      // B k-seg select
    const uint32_t sbB = sb + SM_B;
    const uint32_t sbA = sb + SM_A;

    int gc = 0;
    for (int t = t0; t < t1; t++) {
        const int n0 = t << 7;
        if (tid < 128) t2s[tid] = g_t2[n0 + tid];

        float acc[2][8][4];
#pragma unroll
        for (int mf = 0; mf < 2; mf++)
#pragma unroll
            for (int nf = 0; nf < 8; nf++)
#pragma unroll
                for (int q = 0; q < 4; q++) acc[mf][nf][q] = 0.f;

        for (int c = 0; c < NCH; c++, gc++) {
            CP_WAIT2();                    // chunk gc landed (<=2 groups in flight)
            __syncthreads();               // data visible; buf (gc-1)%4 fully consumed
            issue(gc + 3);                 // refill buf (gc+3)%4 == (gc-1)%4

            const int ac = (c < 8) ? c : (c - 8);       // A: 3rd hi block reuses hi
            const uint32_t ab = sbA + (uint32_t)ac * 16384u;
            const uint32_t bb = sbB + (uint32_t)(gc % NSTAGES) * 16384u;
#pragma unroll
            for (int ks = 0; ks < 4; ks++) {
                uint32_t a0[4], a1[4], bfr[4][4];
                {
                    int r = warp_m * 32 + laA;
                    int sg = ks * 2 + lsA;
                    LDSM_X4(a0, ab + swz(r, sg));
                    r += 16;
                    LDSM_X4(a1, ab + swz(r, sg));
                }
#pragma unroll
                for (int nfp = 0; nfp < 4; nfp++) {
                    int r = warp_n * 64 + nfp * 16 + laB;
                    int sg = ks * 2 + lsB;
                    LDSM_X4(bfr[nfp], bb + swz(r, sg));   // non-trans: [N][K] -> B frag
                }
#pragma unroll
                for (int nf = 0; nf < 8; nf++) {
                    const uint32_t* bp = &bfr[nf >> 1][(nf & 1) * 2];
                    mma16816(acc[0][nf], a0, bp);
                    mma16816(acc[1][nf], a1, bp);
                }
            }
        }

        // ---- epilogue: d = t2 - 2*acc, fused argmin ----
        const int cbase = warp_n * 64 + (lane & 3) * 2;
#pragma unroll
        for (int mf = 0; mf < 2; mf++) {
#pragma unroll
            for (int rr = 0; rr < 2; rr++) {
                float v = 3.0e38f;
                int vi = 0x7fffffff;
#pragma unroll
                for (int nf = 0; nf < 8; nf++) {
                    int col = cbase + nf * 8;
                    float d0 = fmaf(-2.0f, acc[mf][nf][rr * 2 + 0], t2s[col]);
                    float d1 = fmaf(-2.0f, acc[mf][nf][rr * 2 + 1], t2s[col + 1]);
                    if (d0 < v) { v = d0; vi = n0 + col; }
                    if (d1 < v) { v = d1; vi = n0 + col + 1; }
                }
                // quad reduce (lanes differing in bits 0-1 share the row)
#pragma unroll
                for (int off = 1; off <= 2; off <<= 1) {
                    float ov = __shfl_xor_sync(0xffffffffu, v, off);
                    int   oi = __shfl_xor_sync(0xffffffffu, vi, off);
                    if (ov < v || (ov == v && oi < vi)) { v = ov; vi = oi; }
                }
                int row = warp_m * 32 + mf * 16 + (lane >> 2) + rr * 8;
                if (warp_n == 1) {
                    if ((lane & 3) == 0) { exv[row] = v; exi[row] = vi; }
                } else {
                    if (v < rbv[mf][rr] || (v == rbv[mf][rr] && vi < rbi[mf][rr])) {
                        rbv[mf][rr] = v; rbi[mf][rr] = vi;
                    }
                }
            }
        }
        __syncthreads();
        if (warp_n == 0) {
#pragma unroll
            for (int mf = 0; mf < 2; mf++) {
#pragma unroll
                for (int rr = 0; rr < 2; rr++) {
                    int row = warp_m * 32 + mf * 16 + (lane >> 2) + rr * 8;
                    float ov = exv[row];
                    int   oi = exi[row];
                    if (ov < rbv[mf][rr] ||
                        (ov == rbv[mf][rr] && oi < rbi[mf][rr])) {
                        rbv[mf][rr] = ov; rbi[mf][rr] = oi;
                    }
                }
            }
        }
        __syncthreads();   // EX + t2 consumed before next tile rewrites them
    }

    if (warp_n == 0 && (lane & 3) == 0) {
#pragma unroll
        for (int mf = 0; mf < 2; mf++)
#pragma unroll
            for (int rr = 0; rr < 2; rr++) {
                int row = m0 + warp_m * 32 + mf * 16 + (lane >> 2) + rr * 8;
                g_pval[(size_t)row * NSTRIPS + blockIdx.y] = rbv[mf][rr];
                g_pidx[(size_t)row * NSTRIPS + blockIdx.y] = rbi[mf][rr];
            }
    }
}

// ---------------- reduce strips + gather Y ----------------
__global__ void reduce_gather(const float* __restrict__ Y, float* __restrict__ out) {
    int warp = (int)((blockIdx.x * blockDim.x + threadIdx.x) >> 5);  // 0..2047
    int lane = threadIdx.x & 31;
    float v = 3.0e38f;
    int idx = 0x7fffffff;
    if (lane < NSTRIPS) {
        v   = g_pval[(size_t)warp * NSTRIPS + lane];
        idx = g_pidx[(size_t)warp * NSTRIPS + lane];
    }
#pragma unroll
    for (int off = 16; off; off >>= 1) {
        float ov = __shfl_xor_sync(0xffffffffu, v, off);
        int   oi = __shfl_xor_sync(0xffffffffu, idx, off);
        if (ov < v || (ov == v && oi < idx)) { v = ov; idx = oi; }
    }
    if (lane < OUTD)
        out[(size_t)warp * OUTD + lane] = Y[(size_t)idx * OUTD + lane];
}

// ---------------- launch ----------------
extern "C" void kernel_launch(void* const* d_in, const int* in_sizes, int n_in,
                              void* d_out, int out_size) {
    const float* x  = (const float*)d_in[0];     // [2048, 256]
    const float* Xt = (const float*)d_in[1];     // [50000, 256]
    const float* Yt = (const float*)d_in[2];     // [50000, 24]
    float* out = (float*)d_out;                  // [2048, 24]
    (void)in_sizes; (void)n_in; (void)out_size;

    cudaFuncSetAttribute(knn_main, cudaFuncAttributeMaxDynamicSharedMemorySize,
                         SMEM_BYTES);

    prep_query<<<B_ROWS / 8, 256>>>(x);
    prep_train<<<N_PAD / 8, 256>>>(Xt);
    dim3 grid(B_ROWS / MT, NSTRIPS);
    knn_main<<<grid, 256, SMEM_BYTES>>>();
    reduce_gather<<<B_ROWS / 8, 256>>>(Yt, out);
}

// round 13
// speedup vs baseline: 2.1417x; 2.0715x over previous
#include <cuda_runtime.h>
#include <cuda_fp16.h>
#include <cstdint>

// 1-NN via filter + exact re-rank:
//   Phase 1 (fast, approximate): single-term fp16 HMMA GEMM, K=256.
//     For each query row and each 128-column tile of X_train, store
//     tmin[m][tile] = min_n (t2[n] - 2*<hi(x_m), hi(t_n)>)   (no indices).
//     Error of the approximation: sigma ~6e-3 absolute.
//   Phase 2 (exact): per query, rescan every tile with
//     tmin <= gmin + MARGIN (MARGIN=0.5 ~ 80 sigma) in exact fp32 from the
//     ORIGINAL float inputs; argmin with first-min tie rule; gather Y row.

#define B_ROWS   2048
#define N_TRAIN  50000
#define N_PAD    50048        // 391 * 128
#define FEAT     256
#define OUTD     24
#define MT       128
#define NTT      391          // n tiles of 128
#define NSTRIPS  9
#define TPS      44           // ceil(391/9); 9*44=396>=391, t0 always even
#define MARGIN   0.5f

// smem layout (dynamic) for knn_approx
#define SM_T2    0                      // 128 floats
#define SM_EX    512                    // 128 floats (cross-warp min exchange)
#define SM_A     1024                   // 4 sub-chunks x 16384 = 64 KB resident
#define SM_B     (1024 + 4*16384)       // 66560 ; 2 stages x 64 KB ring
#define SMEM_BYTES (SM_B + 2*65536)     // 197632 <= 232448

__device__ __align__(16) __half g_Ah[(size_t)B_ROWS * FEAT];   // hi(x)
__device__ __align__(16) __half g_Bh[(size_t)N_PAD * FEAT];    // hi(t)
__device__ float g_t2[N_PAD];
__device__ float g_tmin[(size_t)B_ROWS * NTT];

// ---------------- PTX helpers (base-arch legal) ----------------
__device__ __forceinline__ uint32_t smem_u32(const void* p) {
    uint32_t a;
    asm("{ .reg .u64 t; cvta.to.shared.u64 t, %1; cvt.u32.u64 %0, t; }"
        : "=r"(a) : "l"(p));
    return a;
}

#define CP_ASYNC16(dst, src) \
    asm volatile("cp.async.cg.shared.global [%0], [%1], 16;" :: "r"(dst), "l"(src) : "memory")
#define CP_COMMIT() asm volatile("cp.async.commit_group;" ::: "memory")
#define CP_WAIT1()  asm volatile("cp.async.wait_group 1;" ::: "memory")

// non-trans ldmatrix: for A ([M][K]) gives the A fragment; for B ([N][K],
// K contiguous) gives exactly the required col-major B fragment.
#define LDSM_X4(r, addr)                                                        \
    asm volatile("ldmatrix.sync.aligned.m8n8.x4.shared.b16 {%0,%1,%2,%3}, [%4];" \
                 : "=r"((r)[0]), "=r"((r)[1]), "=r"((r)[2]), "=r"((r)[3])        \
                 : "r"(addr))

__device__ __forceinline__ void mma16816(float* d, const uint32_t* a,
                                         const uint32_t* b) {
    asm volatile(
        "mma.sync.aligned.m16n8k16.row.col.f32.f16.f16.f32 "
        "{%0,%1,%2,%3}, {%4,%5,%6,%7}, {%8,%9}, {%0,%1,%2,%3};"
        : "+f"(d[0]), "+f"(d[1]), "+f"(d[2]), "+f"(d[3])
        : "r"(a[0]), "r"(a[1]), "r"(a[2]), "r"(a[3]), "r"(b[0]), "r"(b[1]));
}

// swizzled byte offset within a 128x64-half SW128 sub-chunk
__device__ __forceinline__ uint32_t swz(int r, int sg) {
    return (uint32_t)(r * 128 + ((sg ^ (r & 7)) << 4));
}

// ---------------- prep: fp16 hi conversion + t2 ----------------
__global__ void prep_query(const float* __restrict__ X) {
    int w = threadIdx.x >> 5, l = threadIdx.x & 31;
    int row = blockIdx.x * 8 + w;                    // 256*8 = 2048
    const float4* src = reinterpret_cast<const float4*>(X + (size_t)row * FEAT);
    float4 a = src[l * 2], b = src[l * 2 + 1];
    float xs[8] = {a.x, a.y, a.z, a.w, b.x, b.y, b.z, b.w};
    __align__(16) __half h[8];
#pragma unroll
    for (int j = 0; j < 8; j++) h[j] = __float2half_rn(xs[j]);
    reinterpret_cast<uint4*>(g_Ah + (size_t)row * FEAT)[l] =
        *reinterpret_cast<uint4*>(h);
}

__global__ void prep_train(const float* __restrict__ X) {
    int w = threadIdx.x >> 5, l = threadIdx.x & 31;
    int row = blockIdx.x * 8 + w;                    // 6256*8 = 50048
    __align__(16) __half h[8];
    if (row < N_TRAIN) {
        const float4* src = reinterpret_cast<const float4*>(X + (size_t)row * FEAT);
        float4 a = src[l * 2], b = src[l * 2 + 1];
        float xs[8] = {a.x, a.y, a.z, a.w, b.x, b.y, b.z, b.w};
        float ss = 0.f;
#pragma unroll
        for (int j = 0; j < 8; j++) {
            ss += xs[j] * xs[j];
            h[j] = __float2half_rn(xs[j]);
        }
#pragma unroll
        for (int off = 16; off; off >>= 1)
            ss += __shfl_xor_sync(0xffffffffu, ss, off);
        if (l == 0) g_t2[row] = ss;
    } else {
#pragma unroll
        for (int j = 0; j < 8; j++) h[j] = __ushort_as_half((unsigned short)0);
        if (l == 0) g_t2[row] = 1.0e30f;
    }
    reinterpret_cast<uint4*>(g_Bh + (size_t)row * FEAT)[l] =
        *reinterpret_cast<uint4*>(h);
}

// ---------------- phase 1: approx GEMM + per-tile min ----------------
__global__ void __launch_bounds__(256, 1) knn_approx() {
    extern __shared__ char smem[];
    const uint32_t sb = smem_u32(smem);
    const int tid  = threadIdx.x;
    const int wid  = tid >> 5;
    const int lane = tid & 31;
    const int warp_m = wid >> 1;          // 0..3 -> rows 32*warp_m
    const int warp_n = wid & 1;           // 0..1 -> cols 64*warp_n
    const int m0 = blockIdx.x * MT;

    const int t0 = blockIdx.y * TPS;
    int t1 = t0 + TPS; if (t1 > NTT) t1 = NTT;

    const uint4* Bs = reinterpret_cast<const uint4*>(g_Bh);

    // issue full B tile t (128 rows x 256 halves = 64 KB) into stage (t-t0)&1
    auto issue = [&](int t) {
        if (t < t1) {
            int n0 = t << 7;
            uint32_t bb = sb + SM_B + (uint32_t)((t - t0) & 1) * 65536u;
#pragma unroll
            for (int i = 0; i < 16; i++) {
                int idx = tid + (i << 8);          // 0..4095
                int r = idx >> 5;                  // row 0..127
                int s = idx & 31;                  // 16B seg 0..31
                uint32_t dst = bb + (uint32_t)(s >> 3) * 16384u + swz(r, s & 7);
                const uint4* src = Bs + (size_t)(n0 + r) * 32 + s;
                CP_ASYNC16(dst, src);
            }
        }
        CP_COMMIT();
    };

    issue(t0); issue(t0 + 1);

    // resident A tile: 128 rows x 256 halves, 4 SW128 sub-chunks
    {
        const uint4* As = reinterpret_cast<const uint4*>(g_Ah);
#pragma unroll
        for (int i = 0; i < 16; i++) {
            int idx = tid + (i << 8);
            int r = idx >> 5;
            int s = idx & 31;
            uint4 v = As[(size_t)(m0 + r) * 32 + s];
            *reinterpret_cast<uint4*>(smem + SM_A + (s >> 3) * 16384 + swz(r, s & 7)) = v;
        }
    }

    float* t2s = reinterpret_cast<float*>(smem + SM_T2);
    float* exv = reinterpret_cast<float*>(smem + SM_EX);

    const int laA = lane & 15;
    const int lsA = lane >> 4;
    const int laB = (lane & 7) + ((lane >> 4) & 1) * 8;
    const int lsB = (lane >> 3) & 1;
    const uint32_t sbA = sb + SM_A;
    const uint32_t sbB = sb + SM_B;

    for (int t = t0; t < t1; t++) {
        const int n0 = t << 7;
        // safe to write t2s here: all reads of the previous tile's t2s
        // preceded the previous iteration's second __syncthreads
        if (tid < 128) t2s[tid] = g_t2[n0 + tid];

        CP_WAIT1();                    // B stage for tile t landed
        __syncthreads();               // visible to all; exv free; t2s published

        float acc[2][8][4];
#pragma unroll
        for (int mf = 0; mf < 2; mf++)
#pragma unroll
            for (int nf = 0; nf < 8; nf++)
#pragma unroll
                for (int q = 0; q < 4; q++) acc[mf][nf][q] = 0.f;

        const uint32_t bstage = sbB + (uint32_t)((t - t0) & 1) * 65536u;
#pragma unroll
        for (int cc = 0; cc < 4; cc++) {
            const uint32_t ab = sbA + (uint32_t)cc * 16384u;
            const uint32_t bb = bstage + (uint32_t)cc * 16384u;
#pragma unroll
            for (int ks = 0; ks < 4; ks++) {
                uint32_t a0[4], a1[4], bfr[4][4];
                {
                    int r = warp_m * 32 + laA;
                    int sg = ks * 2 + lsA;
                    LDSM_X4(a0, ab + swz(r, sg));
                    r += 16;
                    LDSM_X4(a1, ab + swz(r, sg));
                }
#pragma unroll
                for (int nfp = 0; nfp < 4; nfp++) {
                    int r = warp_n * 64 + nfp * 16 + laB;
                    int sg = ks * 2 + lsB;
                    LDSM_X4(bfr[nfp], bb + swz(r, sg));
                }
#pragma unroll
                for (int nf = 0; nf < 8; nf++) {
                    const uint32_t* bp = &bfr[nf >> 1][(nf & 1) * 2];
                    mma16816(acc[0][nf], a0, bp);
                    mma16816(acc[1][nf], a1, bp);
                }
            }
        }

        // epilogue: per-row tile min of (t2 - 2*cross); no index needed
        const int cbase = warp_n * 64 + (lane & 3) * 2;
        float vloc[2][2];
#pragma unroll
        for (int mf = 0; mf < 2; mf++) {
#pragma unroll
            for (int rr = 0; rr < 2; rr++) {
                float v = 3.0e38f;
#pragma unroll
                for (int nf = 0; nf < 8; nf++) {
                    int col = cbase + nf * 8;
                    float d0 = fmaf(-2.0f, acc[mf][nf][rr * 2 + 0], t2s[col]);
                    float d1 = fmaf(-2.0f, acc[mf][nf][rr * 2 + 1], t2s[col + 1]);
                    v = fminf(v, fminf(d0, d1));
                }
#pragma unroll
                for (int off = 1; off <= 2; off <<= 1)
                    v = fminf(v, __shfl_xor_sync(0xffffffffu, v, off));
                vloc[mf][rr] = v;
                if (warp_n == 1 && (lane & 3) == 0) {
                    int row = warp_m * 32 + mf * 16 + (lane >> 2) + rr * 8;
                    exv[row] = v;
                }
            }
        }
        __syncthreads();               // exv visible; all MMA reads of stage done
        issue(t + 2);                  // refill stage (t&1)
        if (warp_n == 0 && (lane & 3) == 0) {
#pragma unroll
            for (int mf = 0; mf < 2; mf++)
#pragma unroll
                for (int rr = 0; rr < 2; rr++) {
                    int row = warp_m * 32 + mf * 16 + (lane >> 2) + rr * 8;
                    g_tmin[(size_t)(m0 + row) * NTT + t] =
                        fminf(vloc[mf][rr], exv[row]);
                }
        }
    }
}

// ---------------- phase 2: exact re-rank of candidate tiles ----------------
__global__ void __launch_bounds__(128) finalize(
    const float* __restrict__ X, const float* __restrict__ Xt,
    const float* __restrict__ Y, float* __restrict__ out) {
    const int m = blockIdx.x;
    const int tid = threadIdx.x;
    const int wid = tid >> 5;
    const int lane = tid & 31;

    __shared__ float s_tmin[NTT];
    __shared__ __align__(16) float s_xq[FEAT];
    __shared__ float s_red[4];
    __shared__ float s_bv[4];
    __shared__ int   s_bi[4];

    float lmin = 3.0e38f;
    for (int i = tid; i < NTT; i += 128) {
        float v = g_tmin[(size_t)m * NTT + i];
        s_tmin[i] = v;
        lmin = fminf(lmin, v);
    }
#pragma unroll
    for (int off = 16; off; off >>= 1)
        lmin = fminf(lmin, __shfl_xor_sync(0xffffffffu, lmin, off));
    if (lane == 0) s_red[wid] = lmin;
    for (int i = tid; i < FEAT; i += 128) s_xq[i] = X[(size_t)m * FEAT + i];
    __syncthreads();

    const float thr = fminf(fminf(s_red[0], s_red[1]),
                            fminf(s_red[2], s_red[3])) + MARGIN;

    const float4* T4  = reinterpret_cast<const float4*>(Xt);
    const float4* xq4 = reinterpret_cast<const float4*>(s_xq);
    const float4 x0 = xq4[lane * 2];
    const float4 x1 = xq4[lane * 2 + 1];

    float bv = 3.0e38f;
    int   bi = 0x7fffffff;

    for (int t = 0; t < NTT; t++) {
        if (s_tmin[t] > thr) continue;
        const int nb = t * 128 + wid * 32;
#pragma unroll 1
        for (int k = 0; k < 32; k++) {
            int n = nb + k;
            if (n >= N_TRAIN) break;
            float4 p0 = T4[(size_t)n * 64 + lane * 2];
            float4 p1 = T4[(size_t)n * 64 + lane * 2 + 1];
            float s = x0.x * p0.x;
            s = fmaf(x0.y, p0.y, s);
            s = fmaf(x0.z, p0.z, s);
            s = fmaf(x0.w, p0.w, s);
            s = fmaf(x1.x, p1.x, s);
            s = fmaf(x1.y, p1.y, s);
            s = fmaf(x1.z, p1.z, s);
            s = fmaf(x1.w, p1.w, s);
#pragma unroll
            for (int off = 16; off; off >>= 1)
                s += __shfl_xor_sync(0xffffffffu, s, off);
            float d = g_t2[n] - 2.0f * s;
            if (d < bv || (d == bv && n < bi)) { bv = d; bi = n; }
        }
    }

    if (lane == 0) { s_bv[wid] = bv; s_bi[wid] = bi; }
    __syncthreads();
    float fb = 3.0e38f;
    int   fi = 0x7fffffff;
#pragma unroll
    for (int w = 0; w < 4; w++) {
        float ov = s_bv[w]; int oi = s_bi[w];
        if (ov < fb || (ov == fb && oi < fi)) { fb = ov; fi = oi; }
    }
    if (tid < OUTD)
        out[(size_t)m * OUTD + tid] = Y[(size_t)fi * OUTD + tid];
}

// ---------------- launch ----------------
extern "C" void kernel_launch(void* const* d_in, const int* in_sizes, int n_in,
                              void* d_out, int out_size) {
    const float* x  = (const float*)d_in[0];     // [2048, 256]
    const float* Xt = (const float*)d_in[1];     // [50000, 256]
    const float* Yt = (const float*)d_in[2];     // [50000, 24]
    float* out = (float*)d_out;                  // [2048, 24]
    (void)in_sizes; (void)n_in; (void)out_size;

    cudaFuncSetAttribute(knn_approx, cudaFuncAttributeMaxDynamicSharedMemorySize,
                         SMEM_BYTES);

    prep_query<<<B_ROWS / 8, 256>>>(x);
    prep_train<<<N_PAD / 8, 256>>>(Xt);
    dim3 grid(B_ROWS / MT, NSTRIPS);
    knn_approx<<<grid, 256, SMEM_BYTES>>>();
    finalize<<<B_ROWS, 128>>>(x, Xt, Yt, out);
}